// round 6
// baseline (speedup 1.0000x reference)
#include <cuda_runtime.h>
#include <cstdint>

#define S_LEN  2048
#define HEADS  32
#define DDIM   64
#define BQ     128
#define BK     64
#define NTILES (S_LEN / BK)   // 32
#define MASKW  (S_LEN / 32)   // 64 mask words per row

// pair-slot layouts: slot = 4*kk + tg, word = 2*row + pair
#define QPS 264                // Q slot stride (2*128 rows + 8 pad) -> bank step 8
#define KVS 136                // K/V slot stride (2*64 + 8 pad)     -> bank step 8

#define QS_W   (32 * QPS)             // 8448
#define KBUF_W (32 * KVS)             // 4352
#define VBUF_W (32 * KVS)             // 4352
#define SMEM_WORDS (QS_W + 2 * KBUF_W + 2 * VBUF_W)   // 25856
#define SMEM_BYTES (SMEM_WORDS * 4)                   // 103424 -> 2 CTAs/SM

__device__ uint32_t g_maskbits[S_LEN * MASKW];   // 512 KB static scratch

__device__ __forceinline__ uint32_t f2tf(float x) {
    uint32_t r;
    asm("cvt.rna.tf32.f32 %0, %1;" : "=r"(r) : "f"(x));
    return r;
}
__device__ __forceinline__ void mma_tf32(float* d, const uint32_t* a, uint32_t b0, uint32_t b1) {
    asm volatile(
        "mma.sync.aligned.m16n8k8.row.col.f32.tf32.tf32.f32 "
        "{%0,%1,%2,%3}, {%4,%5,%6,%7}, {%8,%9}, {%0,%1,%2,%3};"
        : "+f"(d[0]), "+f"(d[1]), "+f"(d[2]), "+f"(d[3])
        : "r"(a[0]), "r"(a[1]), "r"(a[2]), "r"(a[3]), "r"(b0), "r"(b1));
}

// n-position of logical key r (within-8-group permutation so that the S
// C-fragment lands directly in PV A-fragment layout)
__device__ __forceinline__ int sigma(int r) {
    return (r & ~7) | (((r & 3) << 1) | ((r & 7) >> 2));
}

// ---------------- mask -> bitmask pre-pass ----------------
__global__ void mask_bits_kernel(const int* __restrict__ M) {
    int t = blockIdx.x * 256 + threadIdx.x;
    unsigned w = __ballot_sync(0xffffffffu, M[t] != 0);
    if ((threadIdx.x & 31) == 0) g_maskbits[t >> 5] = w;
}

// ---------------- main kernel ----------------
__global__ void __launch_bounds__(256, 2)
fa_mma3_kernel(const float* __restrict__ Q, const float* __restrict__ K,
               const float* __restrict__ V, float* __restrict__ O) {
    extern __shared__ uint32_t smem[];
    uint32_t* Qs = smem;                     // pair-slot [32][QPS]
    uint32_t* Kb = Qs + QS_W;                // 2 x pair-slot [32][KVS]
    uint32_t* Vb = Kb + 2 * KBUF_W;          // 2 x pair-slot [32][KVS]

    const int tid  = threadIdx.x;
    const int wid  = tid >> 5, lane = tid & 31;
    const int g    = lane >> 2, tg = lane & 3;
    const int bh   = blockIdx.y;
    const int q0   = blockIdx.x * BQ;
    const int rwg  = wid * 16 + g;           // warp's row-g (local, 0..127)

    const float* qb = Q + (size_t)bh * S_LEN * DDIM;
    const float* kb = K + (size_t)bh * S_LEN * DDIM;
    const float* vb = V + (size_t)bh * S_LEN * DDIM;
    float*       ob = O + (size_t)bh * S_LEN * DDIM;

    // ---- stage Q once into pair-slot layout ----
    // float4 at cols 4ch..4ch+3: kk = ch>>1, pair = ch&1, component w -> tg=w
    {
        const int ch = tid & 15, r0 = tid >> 4;
        const int kk = ch >> 1, pr = ch & 1;
        #pragma unroll
        for (int i = 0; i < 8; ++i) {
            int r = r0 + 16 * i;
            float4 v = *(const float4*)&qb[(size_t)(q0 + r) * DDIM + ch * 4];
            uint32_t* base = &Qs[4 * kk * QPS + 2 * r + pr];
            base[0 * QPS] = f2tf(v.x);
            base[1 * QPS] = f2tf(v.y);
            base[2 * QPS] = f2tf(v.z);
            base[3 * QPS] = f2tf(v.w);
        }
    }

    auto stage_kv = [&](int tile, int par) {
        uint32_t* kd = Kb + par * KBUF_W;
        uint32_t* vd = Vb + par * VBUF_W;
        const int k0 = tile * BK;
        // K: pair-slot + sigma row permutation
        {
            const int ch = tid & 15, r0 = tid >> 4;
            const int kk = ch >> 1, pr = ch & 1;
            #pragma unroll
            for (int i = 0; i < 4; ++i) {
                int r = r0 + 16 * i;
                int np = sigma(r);
                float4 v = *(const float4*)&kb[(size_t)(k0 + r) * DDIM + ch * 4];
                uint32_t* base = &kd[4 * kk * KVS + 2 * np + pr];
                base[0 * KVS] = f2tf(v.x);
                base[1 * KVS] = f2tf(v.y);
                base[2 * KVS] = f2tf(v.z);
                base[3 * KVS] = f2tf(v.w);
            }
        }
        // V: slot(4kk+tgs) word 2n: {V[8kk+tgs][n], V[8kk+tgs+4][n]}
        {
            const int n = tid & 63, qq = tid >> 6;
            #pragma unroll
            for (int w = 0; w < 8; ++w) {
                int s = qq * 8 + w;
                int kk = s >> 2, tgs = s & 3;
                float v0 = vb[(size_t)(k0 + 8 * kk + tgs) * DDIM + n];
                float v1 = vb[(size_t)(k0 + 8 * kk + tgs + 4) * DDIM + n];
                uint2 pv = make_uint2(f2tf(v0), f2tf(v1));
                *(uint2*)&vd[s * KVS + 2 * n] = pv;
            }
        }
    };

    stage_kv(0, 0);
    __syncthreads();

    float oacc[8][4];
    #pragma unroll
    for (int j = 0; j < 8; ++j)
        #pragma unroll
        for (int c = 0; c < 4; ++c) oacc[j][c] = 0.f;
    float lsum0 = 0.f, lsum1 = 0.f;

    for (int t = 0; t < NTILES; ++t) {
        const int par = t & 1;
        const uint32_t* kbuf = Kb + par * KBUF_W;
        const uint32_t* vbuf = Vb + par * VBUF_W;

        // ---- S = Q K^T : warp tile 16 x 64, all pair LDS.64 ----
        float sacc[8][4];
        #pragma unroll
        for (int j = 0; j < 8; ++j)
            #pragma unroll
            for (int c = 0; c < 4; ++c) sacc[j][c] = 0.f;

        #pragma unroll
        for (int kk = 0; kk < 8; ++kk) {
            const uint32_t* qp = &Qs[(4 * kk + tg) * QPS + 2 * rwg];
            uint2 a01 = *(const uint2*)qp;          // Q(rwg, tg), Q(rwg, tg+4)
            uint2 a23 = *(const uint2*)(qp + 16);   // rows rwg+8
            uint32_t a[4] = { a01.x, a23.x, a01.y, a23.y };
            const uint32_t* kp = &kbuf[(4 * kk + tg) * KVS + 2 * g];
            #pragma unroll
            for (int j = 0; j < 8; ++j) {
                uint2 b2 = *(const uint2*)(kp + 16 * j);
                mma_tf32(sacc[j], a, b2.x, b2.y);
            }
        }

        // ---- stage next tile (LDG latency hidden behind exp + PV) ----
        if (t + 1 < NTILES) stage_kv(t + 1, par ^ 1);

        // ---- fused: mask + exp -> PV A-frag -> O += P V ----
        const uint2 mw0 = *(const uint2*)&g_maskbits[(size_t)(q0 + rwg) * MASKW + 2 * t];
        const uint2 mw1 = *(const uint2*)&g_maskbits[(size_t)(q0 + rwg + 8) * MASKW + 2 * t];

        #pragma unroll
        for (int kk = 0; kk < 8; ++kk) {
            const uint32_t w0 = (kk < 4) ? mw0.x : mw0.y;
            const uint32_t w1 = (kk < 4) ? mw1.x : mw1.y;
            const int sh = ((kk & 3) << 3) + tg;      // bit of key 8kk+tg
            float e00 = ((w0 >> sh) & 1u)       ? __expf(sacc[kk][0] * 0.125f) : 0.f;
            float e01 = ((w0 >> (sh + 4)) & 1u) ? __expf(sacc[kk][1] * 0.125f) : 0.f;
            float e10 = ((w1 >> sh) & 1u)       ? __expf(sacc[kk][2] * 0.125f) : 0.f;
            float e11 = ((w1 >> (sh + 4)) & 1u) ? __expf(sacc[kk][3] * 0.125f) : 0.f;
            lsum0 += e00 + e01;
            lsum1 += e10 + e11;
            uint32_t a[4] = { f2tf(e00), f2tf(e10), f2tf(e01), f2tf(e11) };

            const uint32_t* vslot = &vbuf[(4 * kk + tg) * KVS + 2 * g];
            #pragma unroll
            for (int j = 0; j < 8; ++j) {
                uint2 b2 = *(const uint2*)(vslot + 16 * j);
                mma_tf32(oacc[j], a, b2.x, b2.y);
            }
        }

        __syncthreads();
    }

    // ---- reduce l across the 4 tg lanes ----
    lsum0 += __shfl_xor_sync(0xffffffffu, lsum0, 1);
    lsum0 += __shfl_xor_sync(0xffffffffu, lsum0, 2);
    lsum1 += __shfl_xor_sync(0xffffffffu, lsum1, 1);
    lsum1 += __shfl_xor_sync(0xffffffffu, lsum1, 2);
    const float inv0 = 1.f / lsum0;
    const float inv1 = 1.f / lsum1;

    // ---- write O (columns natural) ----
    #pragma unroll
    for (int j = 0; j < 8; ++j) {
        float2 o0 = make_float2(oacc[j][0] * inv0, oacc[j][1] * inv0);
        float2 o1 = make_float2(oacc[j][2] * inv1, oacc[j][3] * inv1);
        *(float2*)&ob[(size_t)(q0 + rwg) * DDIM + 8 * j + 2 * tg] = o0;
        *(float2*)&ob[(size_t)(q0 + rwg + 8) * DDIM + 8 * j + 2 * tg] = o1;
    }
}

// ---------------- launch ----------------
extern "C" void kernel_launch(void* const* d_in, const int* in_sizes, int n_in,
                              void* d_out, int out_size) {
    const float* q = (const float*)d_in[0];
    const float* k = (const float*)d_in[1];
    const float* v = (const float*)d_in[2];
    const int*   m = (const int*)d_in[3];
    float* out = (float*)d_out;

    mask_bits_kernel<<<(S_LEN * S_LEN) / 256, 256>>>(m);

    cudaFuncSetAttribute(fa_mma3_kernel,
                         cudaFuncAttributeMaxDynamicSharedMemorySize, SMEM_BYTES);
    dim3 grid(S_LEN / BQ, HEADS);
    fa_mma3_kernel<<<grid, 256, SMEM_BYTES>>>(q, k, v, out);
}

// round 7
// speedup vs baseline: 1.1513x; 1.1513x over previous
#include <cuda_runtime.h>
#include <cstdint>

#define S_LEN  2048
#define HEADS  32
#define DDIM   64
#define BQ     128
#define BK     64
#define NTILES (S_LEN / BK)   // 32
#define MASKW  (S_LEN / 32)   // 64 mask words per row

#define QSTR 68                // Q/K row stride (words): conflict-free frag LDS
#define KSTR 68
#define VSLOT 136              // V (kk,tg) slot stride: conflict-free LDS.64

#define QS_W   (BQ * QSTR)            // 8704
#define KBUF_W (BK * KSTR)            // 4352
#define VBUF_W (32 * VSLOT)           // 4352
#define SMEM_WORDS (QS_W + 2 * KBUF_W + 2 * VBUF_W)   // 26112
#define SMEM_BYTES (SMEM_WORDS * 4)                   // 104448 -> 2 CTAs/SM

__device__ uint32_t g_maskbits[S_LEN * MASKW];   // 512 KB static scratch

__device__ __forceinline__ uint32_t f2tf(float x) {
    uint32_t r;
    asm("cvt.rna.tf32.f32 %0, %1;" : "=r"(r) : "f"(x));
    return r;
}
__device__ __forceinline__ void mma_tf32(float* d, const uint32_t* a, uint32_t b0, uint32_t b1) {
    asm volatile(
        "mma.sync.aligned.m16n8k8.row.col.f32.tf32.tf32.f32 "
        "{%0,%1,%2,%3}, {%4,%5,%6,%7}, {%8,%9}, {%0,%1,%2,%3};"
        : "+f"(d[0]), "+f"(d[1]), "+f"(d[2]), "+f"(d[3])
        : "r"(a[0]), "r"(a[1]), "r"(a[2]), "r"(a[3]), "r"(b0), "r"(b1));
}

// buffer row position of logical key r: C-fragment of S lands directly in the
// PV A-fragment layout (verified bit-identical in R6)
__device__ __forceinline__ int sigma(int r) {
    return (r & ~7) | (((r & 3) << 1) | ((r & 7) >> 2));
}

// ---------------- mask -> bitmask pre-pass ----------------
__global__ void mask_bits_kernel(const int* __restrict__ M) {
    int t = blockIdx.x * 256 + threadIdx.x;
    unsigned w = __ballot_sync(0xffffffffu, M[t] != 0);
    if ((threadIdx.x & 31) == 0) g_maskbits[t >> 5] = w;
}

// ---------------- main kernel ----------------
__global__ void __launch_bounds__(256, 2)
fa_mma4_kernel(const float* __restrict__ Q, const float* __restrict__ K,
               const float* __restrict__ V, float* __restrict__ O) {
    extern __shared__ uint32_t smem[];
    uint32_t* Qs = smem;                     // [128][68]
    uint32_t* Kb = Qs + QS_W;                // 2 x [64][68]  (rows sigma-permuted)
    uint32_t* Vb = Kb + 2 * KBUF_W;          // 2 x [32 slots][136]

    const int tid  = threadIdx.x;
    const int wid  = tid >> 5, lane = tid & 31;
    const int g    = lane >> 2, tg = lane & 3;
    const int bh   = blockIdx.y;
    const int q0   = blockIdx.x * BQ;
    const int rwg  = wid * 16 + g;           // warp's row-g (local, 0..127)

    const float* qb = Q + (size_t)bh * S_LEN * DDIM;
    const float* kb = K + (size_t)bh * S_LEN * DDIM;
    const float* vb = V + (size_t)bh * S_LEN * DDIM;
    float*       ob = O + (size_t)bh * S_LEN * DDIM;

    // ---- stage Q once ----
    {
        const int ch = tid & 15, r0 = tid >> 4;
        #pragma unroll
        for (int i = 0; i < 8; ++i) {
            int r = r0 + 16 * i;
            float4 v = *(const float4*)&qb[(size_t)(q0 + r) * DDIM + ch * 4];
            uint32_t* p = &Qs[r * QSTR + ch * 4];
            p[0] = f2tf(v.x); p[1] = f2tf(v.y); p[2] = f2tf(v.z); p[3] = f2tf(v.w);
        }
    }

    auto stage_kv = [&](int tile, int par) {
        uint32_t* kd = Kb + par * KBUF_W;
        uint32_t* vd = Vb + par * VBUF_W;
        const int k0 = tile * BK;
        // K: natural K-major rows, stored at sigma-permuted row position
        {
            const int ch = tid & 15, r0 = tid >> 4;
            #pragma unroll
            for (int i = 0; i < 4; ++i) {
                int r = r0 + 16 * i;
                float4 v = *(const float4*)&kb[(size_t)(k0 + r) * DDIM + ch * 4];
                uint32_t* p = &kd[sigma(r) * KSTR + ch * 4];
                p[0] = f2tf(v.x); p[1] = f2tf(v.y); p[2] = f2tf(v.z); p[3] = f2tf(v.w);
            }
        }
        // V: slot(4kk+tgs) word 2n: {V[8kk+tgs][n], V[8kk+tgs+4][n]}
        {
            const int n = tid & 63, qq = tid >> 6;
            #pragma unroll
            for (int w = 0; w < 8; ++w) {
                int s = qq * 8 + w;
                int kk = s >> 2, tgs = s & 3;
                float v0 = vb[(size_t)(k0 + 8 * kk + tgs) * DDIM + n];
                float v1 = vb[(size_t)(k0 + 8 * kk + tgs + 4) * DDIM + n];
                uint2 pv = make_uint2(f2tf(v0), f2tf(v1));
                *(uint2*)&vd[s * VSLOT + 2 * n] = pv;
            }
        }
    };

    stage_kv(0, 0);
    __syncthreads();

    float oacc[8][4];
    #pragma unroll
    for (int j = 0; j < 8; ++j)
        #pragma unroll
        for (int c = 0; c < 4; ++c) oacc[j][c] = 0.f;
    float lsum0 = 0.f, lsum1 = 0.f;

    for (int t = 0; t < NTILES; ++t) {
        const int par = t & 1;
        const uint32_t* kbuf = Kb + par * KBUF_W;
        const uint32_t* vbuf = Vb + par * VBUF_W;

        // ---- S = Q K^T : warp tile 16 x 64 (columns sigma-permuted) ----
        float sacc[8][4];
        #pragma unroll
        for (int j = 0; j < 8; ++j)
            #pragma unroll
            for (int c = 0; c < 4; ++c) sacc[j][c] = 0.f;

        #pragma unroll
        for (int kk = 0; kk < 8; ++kk) {
            const int kc = 8 * kk + tg;
            uint32_t a[4];
            const uint32_t* q0p = &Qs[rwg * QSTR + kc];
            const uint32_t* q1p = &Qs[(rwg + 8) * QSTR + kc];
            a[0] = q0p[0]; a[1] = q1p[0]; a[2] = q0p[4]; a[3] = q1p[4];
            #pragma unroll
            for (int j = 0; j < 8; ++j) {
                const uint32_t* kp = &kbuf[(8 * j + g) * KSTR + kc];
                mma_tf32(sacc[j], a, kp[0], kp[4]);
            }
        }

        // ---- stage next tile (LDG latency hidden behind exp + PV) ----
        if (t + 1 < NTILES) stage_kv(t + 1, par ^ 1);

        // ---- mask + exp: thread's S values are keys {8kk+tg, 8kk+tg+4} ----
        uint2 pr0[8], pr1[8];   // pr0: row rwg, pr1: row rwg+8; .x=key tg, .y=key tg+4
        {
            const uint2 mw0 = *(const uint2*)&g_maskbits[(size_t)(q0 + rwg) * MASKW + 2 * t];
            const uint2 mw1 = *(const uint2*)&g_maskbits[(size_t)(q0 + rwg + 8) * MASKW + 2 * t];
            #pragma unroll
            for (int kk = 0; kk < 8; ++kk) {
                const uint32_t w0 = (kk < 4) ? mw0.x : mw0.y;
                const uint32_t w1 = (kk < 4) ? mw1.x : mw1.y;
                const int sh = ((kk & 3) << 3) + tg;      // bit of key 8kk+tg
                float e00 = ((w0 >> sh) & 1u)       ? __expf(sacc[kk][0] * 0.125f) : 0.f;
                float e01 = ((w0 >> (sh + 4)) & 1u) ? __expf(sacc[kk][1] * 0.125f) : 0.f;
                float e10 = ((w1 >> sh) & 1u)       ? __expf(sacc[kk][2] * 0.125f) : 0.f;
                float e11 = ((w1 >> (sh + 4)) & 1u) ? __expf(sacc[kk][3] * 0.125f) : 0.f;
                lsum0 += e00 + e01;
                lsum1 += e10 + e11;
                pr0[kk] = make_uint2(f2tf(e00), f2tf(e01));
                pr1[kk] = make_uint2(f2tf(e10), f2tf(e11));
            }
        }

        // ---- O += P V : A-frags direct from registers, B via paired LDS.64 ----
        #pragma unroll
        for (int kk = 0; kk < 8; ++kk) {
            uint32_t a[4] = { pr0[kk].x, pr1[kk].x, pr0[kk].y, pr1[kk].y };
            const uint32_t* vslot = &vbuf[(kk * 4 + tg) * VSLOT];
            #pragma unroll
            for (int j = 0; j < 8; ++j) {
                uint2 b2 = *(const uint2*)(vslot + 16 * j + 2 * g);
                mma_tf32(oacc[j], a, b2.x, b2.y);
            }
        }

        __syncthreads();
    }

    // ---- reduce l across the 4 tg lanes (rows are warp-private) ----
    lsum0 += __shfl_xor_sync(0xffffffffu, lsum0, 1);
    lsum0 += __shfl_xor_sync(0xffffffffu, lsum0, 2);
    lsum1 += __shfl_xor_sync(0xffffffffu, lsum1, 1);
    lsum1 += __shfl_xor_sync(0xffffffffu, lsum1, 2);
    const float inv0 = 1.f / lsum0;
    const float inv1 = 1.f / lsum1;

    // ---- write O ----
    #pragma unroll
    for (int j = 0; j < 8; ++j) {
        float2 o0 = make_float2(oacc[j][0] * inv0, oacc[j][1] * inv0);
        float2 o1 = make_float2(oacc[j][2] * inv1, oacc[j][3] * inv1);
        *(float2*)&ob[(size_t)(q0 + rwg) * DDIM + 8 * j + 2 * tg] = o0;
        *(float2*)&ob[(size_t)(q0 + rwg + 8) * DDIM + 8 * j + 2 * tg] = o1;
    }
}

// ---------------- launch ----------------
extern "C" void kernel_launch(void* const* d_in, const int* in_sizes, int n_in,
                              void* d_out, int out_size) {
    const float* q = (const float*)d_in[0];
    const float* k = (const float*)d_in[1];
    const float* v = (const float*)d_in[2];
    const int*   m = (const int*)d_in[3];
    float* out = (float*)d_out;

    mask_bits_kernel<<<(S_LEN * S_LEN) / 256, 256>>>(m);

    cudaFuncSetAttribute(fa_mma4_kernel,
                         cudaFuncAttributeMaxDynamicSharedMemorySize, SMEM_BYTES);
    dim3 grid(S_LEN / BQ, HEADS);
    fa_mma4_kernel<<<grid, 256, SMEM_BYTES>>>(q, k, v, out);
}

// round 8
// speedup vs baseline: 1.1532x; 1.0016x over previous
#include <cuda_runtime.h>
#include <cstdint>

#define S_LEN  2048
#define HEADS  32
#define DDIM   64
#define BQ     128
#define BK     64
#define NTILES (S_LEN / BK)   // 32
#define MASKW  (S_LEN / 32)   // 64 mask words per row

#define QPS 264                // Q pair-slot stride (words): 2*128 + 8 pad
#define KVS 136                // K/V pair-slot stride (words): 2*64 + 8 pad

#define QS_W   (32 * QPS)             // 8448 words
#define KBUF_W (32 * KVS)             // 4352 words (17408 B)
#define VBUF_W (32 * KVS)             // 4352 words
#define KBUF_BYTES (KBUF_W * 4)
#define SMEM_WORDS (QS_W + 2 * KBUF_W + 2 * VBUF_W)   // 25856
#define SMEM_BYTES (SMEM_WORDS * 4)                   // 103424 -> 2 CTAs/SM

__device__ uint32_t g_maskbits[S_LEN * MASKW];             // 512 KB
__device__ uint32_t g_Kp[(size_t)HEADS * NTILES * KBUF_W]; // ~17.8 MB packed K
__device__ uint32_t g_Vp[(size_t)HEADS * NTILES * VBUF_W]; // ~17.8 MB packed V

__device__ __forceinline__ uint32_t f2tf(float x) {
    uint32_t r;
    asm("cvt.rna.tf32.f32 %0, %1;" : "=r"(r) : "f"(x));
    return r;
}
__device__ __forceinline__ float ex2f(float x) {
    float r;
    asm("ex2.approx.f32 %0, %1;" : "=f"(r) : "f"(x));
    return r;
}
__device__ __forceinline__ void mma_tf32(float* d, const uint32_t* a, uint32_t b0, uint32_t b1) {
    asm volatile(
        "mma.sync.aligned.m16n8k8.row.col.f32.tf32.tf32.f32 "
        "{%0,%1,%2,%3}, {%4,%5,%6,%7}, {%8,%9}, {%0,%1,%2,%3};"
        : "+f"(d[0]), "+f"(d[1]), "+f"(d[2]), "+f"(d[3])
        : "r"(a[0]), "r"(a[1]), "r"(a[2]), "r"(a[3]), "r"(b0), "r"(b1));
}
__device__ __forceinline__ uint32_t smem_u32(const void* p) {
    uint32_t a;
    asm("{ .reg .u64 t; cvta.to.shared.u64 t, %1; cvt.u32.u64 %0, t; }" : "=r"(a) : "l"(p));
    return a;
}
__device__ __forceinline__ void cpa16(uint32_t s, const void* g) {
    asm volatile("cp.async.cg.shared.global [%0], [%1], 16;" :: "r"(s), "l"(g));
}
#define CP_COMMIT() asm volatile("cp.async.commit_group;" ::: "memory")
#define CP_WAIT1()  asm volatile("cp.async.wait_group 1;" ::: "memory")

// sigma^-1: logical key row stored at buffer position p (R7-verified permutation)
__device__ __forceinline__ int sinv(int p) {
    return (p & ~7) | ((p & 1) << 2) | ((p & 7) >> 1);
}

// ---------------- mask -> bitmask pre-pass ----------------
__global__ void mask_bits_kernel(const int* __restrict__ M) {
    int t = blockIdx.x * 256 + threadIdx.x;
    unsigned w = __ballot_sync(0xffffffffu, M[t] != 0);
    if ((threadIdx.x & 31) == 0) g_maskbits[t >> 5] = w;
}

// ---------------- K/V pack pre-pass: tf32 + sigma + pair-slot smem image ----
__global__ void kv_pack_kernel(const float* __restrict__ K, const float* __restrict__ V) {
    const int t = blockIdx.x, h = blockIdx.y;
    const int tid = threadIdx.x;
    const int p = tid & 63, half = tid >> 6;
    const size_t gbase = (size_t)h * S_LEN * DDIM + (size_t)t * BK * DDIM;
    uint32_t* kd = g_Kp + ((size_t)h * NTILES + t) * KBUF_W;
    uint32_t* vd = g_Vp + ((size_t)h * NTILES + t) * VBUF_W;
    const int r = sinv(p);   // logical K row landing at buffer position p

    #pragma unroll
    for (int si = 0; si < 8; ++si) {
        const int slot = half * 8 + si;
        const int kk = slot >> 2, tgs = slot & 3;
        float ka  = K[gbase + (size_t)r * DDIM + 8 * kk + tgs];
        float kb2 = K[gbase + (size_t)r * DDIM + 8 * kk + tgs + 4];
        *(uint2*)&kd[slot * KVS + 2 * p] = make_uint2(f2tf(ka), f2tf(kb2));
        float va  = V[gbase + (size_t)(8 * kk + tgs) * DDIM + p];
        float vb2 = V[gbase + (size_t)(8 * kk + tgs + 4) * DDIM + p];
        *(uint2*)&vd[slot * KVS + 2 * p] = make_uint2(f2tf(va), f2tf(vb2));
    }
}

// ---------------- main kernel ----------------
__global__ void __launch_bounds__(256, 2)
fa_mma5_kernel(const float* __restrict__ Q, float* __restrict__ O) {
    extern __shared__ uint32_t smem[];
    uint32_t* Qs = smem;                     // pair-slot [32][QPS]
    uint32_t* Kb = Qs + QS_W;                // 2 x pair-slot [32][KVS]
    uint32_t* Vb = Kb + 2 * KBUF_W;          // 2 x pair-slot [32][KVS]
    const uint32_t sb = smem_u32(smem);
    const uint32_t sb_k = sb + 4 * QS_W;
    const uint32_t sb_v = sb_k + 2 * KBUF_BYTES;

    const int tid  = threadIdx.x;
    const int wid  = tid >> 5, lane = tid & 31;
    const int g    = lane >> 2, tg = lane & 3;
    const int bh   = blockIdx.y;
    const int q0   = blockIdx.x * BQ;
    const int rwg  = wid * 16 + g;

    const float* qb = Q + (size_t)bh * S_LEN * DDIM;
    float*       ob = O + (size_t)bh * S_LEN * DDIM;
    const char*  kgb = (const char*)(g_Kp + (size_t)bh * NTILES * KBUF_W);
    const char*  vgb = (const char*)(g_Vp + (size_t)bh * NTILES * VBUF_W);

    // ---- stage Q once into pair-slot layout ----
    {
        const int qr = tid & 127, mg = tid >> 7;
        #pragma unroll
        for (int i = 0; i < 4; ++i) {
            const int mm = mg + 2 * i;
            float4 va = *(const float4*)&qb[(size_t)(q0 + qr) * DDIM + 8 * mm];
            float4 vc = *(const float4*)&qb[(size_t)(q0 + qr) * DDIM + 8 * mm + 4];
            uint32_t* base = &Qs[(4 * mm) * QPS + 2 * qr];
            *(uint2*)&base[0 * QPS] = make_uint2(f2tf(va.x), f2tf(vc.x));
            *(uint2*)&base[1 * QPS] = make_uint2(f2tf(va.y), f2tf(vc.y));
            *(uint2*)&base[2 * QPS] = make_uint2(f2tf(va.z), f2tf(vc.z));
            *(uint2*)&base[3 * QPS] = make_uint2(f2tf(va.w), f2tf(vc.w));
        }
    }

    auto issue_kv = [&](int tile, int par) {
        const char* kg = kgb + (size_t)tile * KBUF_BYTES;
        const char* vg = vgb + (size_t)tile * KBUF_BYTES;
        const uint32_t ks = sb_k + par * KBUF_BYTES;
        const uint32_t vs = sb_v + par * KBUF_BYTES;
        #pragma unroll
        for (int i = 0; i < 4; ++i) {
            const int c = tid + 256 * i;
            cpa16(ks + 16 * c, kg + 16 * c);
            cpa16(vs + 16 * c, vg + 16 * c);
        }
        if (tid < 64) {
            const int c = tid + 1024;
            cpa16(ks + 16 * c, kg + 16 * c);
            cpa16(vs + 16 * c, vg + 16 * c);
        }
    };

    issue_kv(0, 0); CP_COMMIT();
    issue_kv(1, 1); CP_COMMIT();

    float oacc[8][4];
    #pragma unroll
    for (int j = 0; j < 8; ++j)
        #pragma unroll
        for (int c = 0; c < 4; ++c) oacc[j][c] = 0.f;
    float lsum0 = 0.f, lsum1 = 0.f;

    const float EC = 0.18033688011112042f;   // 0.125 * log2(e)

    for (int t = 0; t < NTILES; ++t) {
        const int par = t & 1;
        const uint32_t* kbuf = Kb + par * KBUF_W;
        const uint32_t* vbuf = Vb + par * VBUF_W;

        CP_WAIT1();
        __syncthreads();

        // ---- S = Q K^T : warp tile 16 x 64, all LDS.64 ----
        float sacc[8][4];
        #pragma unroll
        for (int j = 0; j < 8; ++j)
            #pragma unroll
            for (int c = 0; c < 4; ++c) sacc[j][c] = 0.f;

        #pragma unroll
        for (int kk = 0; kk < 8; ++kk) {
            const uint32_t* qp = &Qs[(4 * kk + tg) * QPS + 2 * rwg];
            uint2 a01 = *(const uint2*)qp;
            uint2 a23 = *(const uint2*)(qp + 16);
            uint32_t a[4] = { a01.x, a23.x, a01.y, a23.y };
            const uint32_t* kp = &kbuf[(4 * kk + tg) * KVS + 2 * g];
            #pragma unroll
            for (int j = 0; j < 8; ++j) {
                uint2 b2 = *(const uint2*)(kp + 16 * j);
                mma_tf32(sacc[j], a, b2.x, b2.y);
            }
        }

        // ---- mask + exp: thread's S values are keys {8kk+tg, 8kk+tg+4} ----
        uint2 pr0[8], pr1[8];
        {
            const uint2 mw0 = *(const uint2*)&g_maskbits[(size_t)(q0 + rwg) * MASKW + 2 * t];
            const uint2 mw1 = *(const uint2*)&g_maskbits[(size_t)(q0 + rwg + 8) * MASKW + 2 * t];
            #pragma unroll
            for (int kk = 0; kk < 8; ++kk) {
                const uint32_t w0 = (kk < 4) ? mw0.x : mw0.y;
                const uint32_t w1 = (kk < 4) ? mw1.x : mw1.y;
                const int sh = ((kk & 3) << 3) + tg;
                float e00 = ((w0 >> sh) & 1u)       ? ex2f(sacc[kk][0] * EC) : 0.f;
                float e01 = ((w0 >> (sh + 4)) & 1u) ? ex2f(sacc[kk][1] * EC) : 0.f;
                float e10 = ((w1 >> sh) & 1u)       ? ex2f(sacc[kk][2] * EC) : 0.f;
                float e11 = ((w1 >> (sh + 4)) & 1u) ? ex2f(sacc[kk][3] * EC) : 0.f;
                lsum0 += e00 + e01;
                lsum1 += e10 + e11;
                pr0[kk] = make_uint2(f2tf(e00), f2tf(e01));
                pr1[kk] = make_uint2(f2tf(e10), f2tf(e11));
            }
        }

        // ---- O += P V ----
        #pragma unroll
        for (int kk = 0; kk < 8; ++kk) {
            uint32_t a[4] = { pr0[kk].x, pr1[kk].x, pr0[kk].y, pr1[kk].y };
            const uint32_t* vslot = &vbuf[(kk * 4 + tg) * KVS];
            #pragma unroll
            for (int j = 0; j < 8; ++j) {
                uint2 b2 = *(const uint2*)(vslot + 16 * j + 2 * g);
                mma_tf32(oacc[j], a, b2.x, b2.y);
            }
        }

        __syncthreads();
        if (t + 2 < NTILES) issue_kv(t + 2, par);
        CP_COMMIT();
    }

    lsum0 += __shfl_xor_sync(0xffffffffu, lsum0, 1);
    lsum0 += __shfl_xor_sync(0xffffffffu, lsum0, 2);
    lsum1 += __shfl_xor_sync(0xffffffffu, lsum1, 1);
    lsum1 += __shfl_xor_sync(0xffffffffu, lsum1, 2);
    const float inv0 = 1.f / lsum0;
    const float inv1 = 1.f / lsum1;

    #pragma unroll
    for (int j = 0; j < 8; ++j) {
        float2 o0 = make_float2(oacc[j][0] * inv0, oacc[j][1] * inv0);
        float2 o1 = make_float2(oacc[j][2] * inv1, oacc[j][3] * inv1);
        *(float2*)&ob[(size_t)(q0 + rwg) * DDIM + 8 * j + 2 * tg] = o0;
        *(float2*)&ob[(size_t)(q0 + rwg + 8) * DDIM + 8 * j + 2 * tg] = o1;
    }
}

// ---------------- launch ----------------
extern "C" void kernel_launch(void* const* d_in, const int* in_sizes, int n_in,
                              void* d_out, int out_size) {
    const float* q = (const float*)d_in[0];
    const float* k = (const float*)d_in[1];
    const float* v = (const float*)d_in[2];
    const int*   m = (const int*)d_in[3];
    float* out = (float*)d_out;

    mask_bits_kernel<<<(S_LEN * S_LEN) / 256, 256>>>(m);
    kv_pack_kernel<<<dim3(NTILES, HEADS), 256>>>(k, v);

    cudaFuncSetAttribute(fa_mma5_kernel,
                         cudaFuncAttributeMaxDynamicSharedMemorySize, SMEM_BYTES);
    dim3 grid(S_LEN / BQ, HEADS);
    fa_mma5_kernel<<<grid, 256, SMEM_BYTES>>>(q, out);
}

// round 9
// speedup vs baseline: 2.0100x; 1.7430x over previous
#include <cuda_runtime.h>
#include <cstdint>

#define S_LEN  2048
#define HEADS  32
#define DDIM   64
#define BQ     128
#define BK     64
#define NTILES (S_LEN / BK)   // 32
#define MASKW  (S_LEN / 32)   // 64 mask words per row

#define SLOTW  136                    // pair-slot stride in u32 (2*64 + 8 pad)
#define KIMG_W (16 * SLOTW)           // 2176 u32 = 8704 B  (one K or V tile image)
#define TILE_W (2 * KIMG_W)           // 4352 u32 = 17408 B (K + V)
#define TILE_BYTES (TILE_W * 4)
#define SMEM_U32 (2 * TILE_W)         // 8704 u32 = 34816 B (double buffer)

__device__ uint32_t g_maskbits[S_LEN * MASKW];                 // 512 KB
__device__ uint32_t g_KVp[(size_t)HEADS * NTILES * TILE_W];    // ~17.8 MB packed K+V (fp16)

__device__ __forceinline__ uint32_t packh2(float lo, float hi) {
    uint32_t r;   // d = {hi(first op) : lo(second op)}
    asm("cvt.rn.f16x2.f32 %0, %1, %2;" : "=r"(r) : "f"(hi), "f"(lo));
    return r;
}
__device__ __forceinline__ float ex2f(float x) {
    float r;
    asm("ex2.approx.f32 %0, %1;" : "=f"(r) : "f"(x));
    return r;
}
__device__ __forceinline__ void mma_f16(float* d, const uint32_t* a, uint32_t b0, uint32_t b1) {
    asm volatile(
        "mma.sync.aligned.m16n8k16.row.col.f32.f16.f16.f32 "
        "{%0,%1,%2,%3}, {%4,%5,%6,%7}, {%8,%9}, {%0,%1,%2,%3};"
        : "+f"(d[0]), "+f"(d[1]), "+f"(d[2]), "+f"(d[3])
        : "r"(a[0]), "r"(a[1]), "r"(a[2]), "r"(a[3]), "r"(b0), "r"(b1));
}
__device__ __forceinline__ uint32_t smem_u32(const void* p) {
    uint32_t a;
    asm("{ .reg .u64 t; cvta.to.shared.u64 t, %1; cvt.u32.u64 %0, t; }" : "=r"(a) : "l"(p));
    return a;
}
__device__ __forceinline__ void cpa16(uint32_t s, const void* g) {
    asm volatile("cp.async.cg.shared.global [%0], [%1], 16;" :: "r"(s), "l"(g));
}
#define CP_COMMIT() asm volatile("cp.async.commit_group;" ::: "memory")
#define CP_WAIT1()  asm volatile("cp.async.wait_group 1;" ::: "memory")

// ---------------- mask -> bitmask pre-pass ----------------
__global__ void mask_bits_kernel(const int* __restrict__ M) {
    int t = blockIdx.x * 256 + threadIdx.x;
    unsigned w = __ballot_sync(0xffffffffu, M[t] != 0);
    if ((threadIdx.x & 31) == 0) g_maskbits[t >> 5] = w;
}

// ---------------- K/V pack pre-pass: fp16 pair-slot smem images ----------------
// K image, slot s=4kk+tg, u32 offset 2r  : {h2(K[r][16kk+2tg..]), h2(K[r][16kk+2tg+8..])}
// V image, slot s=4kk+tg, u32 offset 2n  : {h2(V[16kk+2tg..][n]), h2(V[16kk+2tg+8..][n])}
__global__ void kv_pack_kernel(const float* __restrict__ K, const float* __restrict__ V) {
    const int t = blockIdx.x, h = blockIdx.y;
    const int tid = threadIdx.x;
    const int r = tid & 63, sg = tid >> 6;
    const float* kbT = K + (size_t)h * S_LEN * DDIM + (size_t)t * BK * DDIM;
    const float* vbT = V + (size_t)h * S_LEN * DDIM + (size_t)t * BK * DDIM;
    uint32_t* kd = g_KVp + ((size_t)h * NTILES + t) * TILE_W;
    uint32_t* vd = kd + KIMG_W;

    #pragma unroll
    for (int si = 0; si < 4; ++si) {
        const int slot = 4 * si + sg;
        const int kk = slot >> 2, tg = slot & 3;
        const int c0 = 16 * kk + 2 * tg;
        // K
        float2 ka = *(const float2*)&kbT[(size_t)r * DDIM + c0];
        float2 kc = *(const float2*)&kbT[(size_t)r * DDIM + c0 + 8];
        *(uint2*)&kd[slot * SLOTW + 2 * r] =
            make_uint2(packh2(ka.x, ka.y), packh2(kc.x, kc.y));
        // V (n = r)
        float v0 = vbT[(size_t)(c0 + 0) * DDIM + r];
        float v1 = vbT[(size_t)(c0 + 1) * DDIM + r];
        float v8 = vbT[(size_t)(c0 + 8) * DDIM + r];
        float v9 = vbT[(size_t)(c0 + 9) * DDIM + r];
        *(uint2*)&vd[slot * SLOTW + 2 * r] =
            make_uint2(packh2(v0, v1), packh2(v8, v9));
    }
}

// ---------------- main kernel ----------------
__global__ void __launch_bounds__(256, 2)
fa_f16_kernel(const float* __restrict__ Q, float* __restrict__ O) {
    __shared__ uint32_t smem[SMEM_U32];
    const uint32_t sb = smem_u32(smem);

    const int tid  = threadIdx.x;
    const int wid  = tid >> 5, lane = tid & 31;
    const int g    = lane >> 2, tg = lane & 3;
    const int bh   = blockIdx.y;
    const int q0   = blockIdx.x * BQ;
    const int rwg  = wid * 16 + g;           // warp row-g (local, 0..127)

    const float* qb = Q + (size_t)bh * S_LEN * DDIM;
    float*       ob = O + (size_t)bh * S_LEN * DDIM;
    const char*  kvb = (const char*)(g_KVp + (size_t)bh * NTILES * TILE_W);

    // ---- Q fragments for the whole kernel: 16 regs, loaded once from global ----
    uint32_t qfrag[4][4];
    {
        const float* qr0 = &qb[(size_t)(q0 + rwg) * DDIM];
        const float* qr1 = &qb[(size_t)(q0 + rwg + 8) * DDIM];
        #pragma unroll
        for (int kk = 0; kk < 4; ++kk) {
            const int c0 = 16 * kk + 2 * tg;
            float2 x0 = *(const float2*)&qr0[c0];
            float2 x1 = *(const float2*)&qr1[c0];
            float2 x2 = *(const float2*)&qr0[c0 + 8];
            float2 x3 = *(const float2*)&qr1[c0 + 8];
            qfrag[kk][0] = packh2(x0.x, x0.y);
            qfrag[kk][1] = packh2(x1.x, x1.y);
            qfrag[kk][2] = packh2(x2.x, x2.y);
            qfrag[kk][3] = packh2(x3.x, x3.y);
        }
    }

    auto issue_kv = [&](int tile, int par) {
        const char* src = kvb + (size_t)tile * TILE_BYTES;
        const uint32_t dst = sb + par * TILE_BYTES;
        #pragma unroll
        for (int i = 0; i < 4; ++i) {
            const int c = tid + 256 * i;
            cpa16(dst + 16 * c, src + 16 * c);
        }
        if (tid < 64) {
            const int c = tid + 1024;
            cpa16(dst + 16 * c, src + 16 * c);
        }
    };

    issue_kv(0, 0); CP_COMMIT();
    issue_kv(1, 1); CP_COMMIT();

    float oacc[8][4];
    #pragma unroll
    for (int j = 0; j < 8; ++j)
        #pragma unroll
        for (int c = 0; c < 4; ++c) oacc[j][c] = 0.f;
    float lsum0 = 0.f, lsum1 = 0.f;

    const float EC = 0.18033688011112042f;   // 0.125 * log2(e)

    for (int t = 0; t < NTILES; ++t) {
        const int par = t & 1;
        const uint32_t* kbuf = smem + par * TILE_W;
        const uint32_t* vbuf = kbuf + KIMG_W;

        CP_WAIT1();
        __syncthreads();

        // ---- S = Q K^T : warp tile 16 x 64, 32 mma (4 k16-steps x 8 j) ----
        float sacc[8][4];
        #pragma unroll
        for (int j = 0; j < 8; ++j)
            #pragma unroll
            for (int c = 0; c < 4; ++c) sacc[j][c] = 0.f;

        #pragma unroll
        for (int kk = 0; kk < 4; ++kk) {
            const uint32_t* kp = &kbuf[(4 * kk + tg) * SLOTW + 2 * g];
            #pragma unroll
            for (int j = 0; j < 8; ++j) {
                uint2 b2 = *(const uint2*)(kp + 16 * j);
                mma_f16(sacc[j], qfrag[kk], b2.x, b2.y);
            }
        }

        // ---- mask + exp: thread's S cols are keys {8j+2tg, 8j+2tg+1} ----
        uint2 pr[8];   // .x = rows rwg (c0,c1 packed), .y = rows rwg+8
        {
            const uint2 mw0 = *(const uint2*)&g_maskbits[(size_t)(q0 + rwg) * MASKW + 2 * t];
            const uint2 mw1 = *(const uint2*)&g_maskbits[(size_t)(q0 + rwg + 8) * MASKW + 2 * t];
            #pragma unroll
            for (int j = 0; j < 8; ++j) {
                const uint32_t w0 = (j < 4) ? mw0.x : mw0.y;
                const uint32_t w1 = (j < 4) ? mw1.x : mw1.y;
                const int sh = ((j & 3) << 3) + 2 * tg;
                float e00 = ((w0 >> sh) & 1u)       ? ex2f(sacc[j][0] * EC) : 0.f;
                float e01 = ((w0 >> (sh + 1)) & 1u) ? ex2f(sacc[j][1] * EC) : 0.f;
                float e10 = ((w1 >> sh) & 1u)       ? ex2f(sacc[j][2] * EC) : 0.f;
                float e11 = ((w1 >> (sh + 1)) & 1u) ? ex2f(sacc[j][3] * EC) : 0.f;
                lsum0 += e00 + e01;
                lsum1 += e10 + e11;
                pr[j] = make_uint2(packh2(e00, e01), packh2(e10, e11));
            }
        }

        // ---- O += P V : A-frags are pr[2kk],pr[2kk+1] verbatim, 32 mma ----
        #pragma unroll
        for (int kk = 0; kk < 4; ++kk) {
            uint32_t a[4] = { pr[2 * kk].x, pr[2 * kk].y, pr[2 * kk + 1].x, pr[2 * kk + 1].y };
            const uint32_t* vp = &vbuf[(4 * kk + tg) * SLOTW + 2 * g];
            #pragma unroll
            for (int j = 0; j < 8; ++j) {
                uint2 b2 = *(const uint2*)(vp + 16 * j);
                mma_f16(oacc[j], a, b2.x, b2.y);
            }
        }

        __syncthreads();
        if (t + 2 < NTILES) issue_kv(t + 2, par);
        CP_COMMIT();
    }

    // ---- reduce l across the 4 tg lanes (rows are warp-private) ----
    lsum0 += __shfl_xor_sync(0xffffffffu, lsum0, 1);
    lsum0 += __shfl_xor_sync(0xffffffffu, lsum0, 2);
    lsum1 += __shfl_xor_sync(0xffffffffu, lsum1, 1);
    lsum1 += __shfl_xor_sync(0xffffffffu, lsum1, 2);
    const float inv0 = 1.f / lsum0;
    const float inv1 = 1.f / lsum1;

    // ---- write O ----
    #pragma unroll
    for (int j = 0; j < 8; ++j) {
        float2 o0 = make_float2(oacc[j][0] * inv0, oacc[j][1] * inv0);
        float2 o1 = make_float2(oacc[j][2] * inv1, oacc[j][3] * inv1);
        *(float2*)&ob[(size_t)(q0 + rwg) * DDIM + 8 * j + 2 * tg] = o0;
        *(float2*)&ob[(size_t)(q0 + rwg + 8) * DDIM + 8 * j + 2 * tg] = o1;
    }
}

// ---------------- launch ----------------
extern "C" void kernel_launch(void* const* d_in, const int* in_sizes, int n_in,
                              void* d_out, int out_size) {
    const float* q = (const float*)d_in[0];
    const float* k = (const float*)d_in[1];
    const float* v = (const float*)d_in[2];
    const int*   m = (const int*)d_in[3];
    float* out = (float*)d_out;

    mask_bits_kernel<<<(S_LEN * S_LEN) / 256, 256>>>(m);
    kv_pack_kernel<<<dim3(NTILES, HEADS), 256>>>(k, v);

    dim3 grid(S_LEN / BQ, HEADS);
    fa_f16_kernel<<<grid, 256>>>(q, out);
}